// round 6
// baseline (speedup 1.0000x reference)
#include <cuda_runtime.h>
#include <cuda_bf16.h>
#include <math.h>

#define BB     2
#define CC     256
#define NQ     4096
#define HEADS  4
#define DH     64
#define KK     64
#define GROUPS 32
#define CPG    8
#define EPS    1e-6f

#define PAD_A  136      // [c][n] layout pad: 136 mod 32 = 8 -> conflict-free
#define PAD_B  36       // [row][c] layout pad: 36 mod 32 = 4 -> conflict-free

// Scratch (device globals; no allocation allowed)
__device__ float         g_qt[BB*NQ*CC];   // Q fp32, [b][n][c]  c = head*64 + d
__device__ __nv_bfloat16 g_kb[BB*NQ*CC];   // K bf16, [b][n][c]
__device__ __nv_bfloat16 g_vb[BB*NQ*CC];   // V bf16, [b][n][c]
__device__ float         g_at[BB*NQ*CC];   // attn out, [b][n][c] c = d*HEADS + h
__device__ float         g_mean[BB][GROUPS];
__device__ float         g_rstd[BB][GROUPS];
__device__ float         g_wp[BB*3*CC*CC]; // GN-folded weights [b][which][o][c]
__device__ float         g_bp[BB*3*CC];    // GN-folded biases

// ---------------------------------------------------------------------------
// helpers
// ---------------------------------------------------------------------------
__device__ __forceinline__ void mma1688(float d[4], const unsigned a[4],
                                        const unsigned b[2]) {
    asm("mma.sync.aligned.m16n8k8.row.col.f32.tf32.tf32.f32 "
        "{%0,%1,%2,%3}, {%4,%5,%6,%7}, {%8,%9}, {%0,%1,%2,%3};"
        : "+f"(d[0]), "+f"(d[1]), "+f"(d[2]), "+f"(d[3])
        : "r"(a[0]), "r"(a[1]), "r"(a[2]), "r"(a[3]),
          "r"(b[0]), "r"(b[1]));
}

__device__ __forceinline__ void cp16(unsigned dst, const void* src) {
    asm volatile("cp.async.cg.shared.global [%0], [%1], 16;"
                 :: "r"(dst), "l"(src));
}
#define CP_COMMIT() asm volatile("cp.async.commit_group;")
#define CP_WAIT(n)  asm volatile("cp.async.wait_group %0;" :: "n"(n))

// ---------------------------------------------------------------------------
// GroupNorm statistics only: grid (GROUPS, B), block 256
// ---------------------------------------------------------------------------
__global__ void gn_stats(const float* __restrict__ x)
{
    const int g = blockIdx.x, b = blockIdx.y;
    const float* xp = x + ((size_t)b*CC + g*CPG) * NQ;
    const int tid = threadIdx.x;
    const int NE  = CPG * NQ;

    float s = 0.f, s2 = 0.f;
    for (int i = tid; i < NE; i += 256) {
        float v = xp[i];
        s += v; s2 += v * v;
    }
    #pragma unroll
    for (int o = 16; o; o >>= 1) {
        s  += __shfl_xor_sync(~0u, s,  o);
        s2 += __shfl_xor_sync(~0u, s2, o);
    }
    __shared__ float shs[8], shs2[8];
    int w = tid >> 5, l = tid & 31;
    if (l == 0) { shs[w] = s; shs2[w] = s2; }
    __syncthreads();
    if (tid == 0) {
        float a = 0.f, c = 0.f;
        #pragma unroll
        for (int i = 0; i < 8; i++) { a += shs[i]; c += shs2[i]; }
        float m   = a / NE;
        float var = c / NE - m * m;
        g_mean[b][g] = m;
        g_rstd[b][g] = rsqrtf(var + EPS);
    }
}

// ---------------------------------------------------------------------------
// Fold GN into QKV weights: W'_oc = W_oc * s_c * r_g(c),
// bias'_o = b_o + sum_c W_oc * (beta_c - m_g * r_g * s_c).
// grid (3, B), block 256 (8 warps, each handles 32 o-rows).
// ---------------------------------------------------------------------------
__global__ void wprep(const float* __restrict__ wq, const float* __restrict__ bq,
                      const float* __restrict__ wk, const float* __restrict__ bk,
                      const float* __restrict__ wv, const float* __restrict__ bv,
                      const float* __restrict__ gsc, const float* __restrict__ gbi)
{
    const int which = blockIdx.x, b = blockIdx.y;
    const float* W    = which == 0 ? wq : which == 1 ? wk : wv;
    const float* bias = which == 0 ? bq : which == 1 ? bk : bv;

    __shared__ float coef[CC], sub[CC];
    const int tid = threadIdx.x;
    {
        int c = tid;
        int g = c >> 3;            // c / CPG
        float r = g_rstd[b][g], m = g_mean[b][g];
        float sc = gsc[c];
        coef[c] = sc * r;
        sub[c]  = gbi[c] - m * r * sc;
    }
    __syncthreads();

    float* Wp = g_wp + (size_t)(b*3 + which) * CC * CC;
    float* bp = g_bp + (b*3 + which) * CC;
    const int wid = tid >> 5, lane = tid & 31;

    for (int o = wid; o < CC; o += 8) {
        float acc = 0.f;
        #pragma unroll
        for (int cb = 0; cb < CC; cb += 32) {
            int c = cb + lane;
            float w = W[(size_t)o * CC + c];
            Wp[(size_t)o * CC + c] = w * coef[c];
            acc += w * sub[c];
        }
        #pragma unroll
        for (int off = 16; off; off >>= 1)
            acc += __shfl_xor_sync(~0u, acc, off);
        if (lane == 0) bp[o] = bias[o] + acc;
    }
}

// ---------------------------------------------------------------------------
// Fused QKV GEMM (tf32 MMA, cp.async double-buffered, GN folded):
// O[b][n][o] = sum_c W'[o][c] * x[b][c][n] + bias'[o]
// Tile 128(n=M) x 64(o=N), 128 threads (4 warps 2x2, warp 64x32), k-step 32.
// grid (NQ/128, 12, B): y>>2 = which, (y&3)*64 = o-block.
// ---------------------------------------------------------------------------
#define QKV_SMEM ((2*32*PAD_A + 2*64*PAD_B) * 4)

__global__ void __launch_bounds__(128)
gemm_qkv(const float* __restrict__ x)
{
    extern __shared__ unsigned smem_dyn[];
    unsigned* As = smem_dyn;                 // [2][32][PAD_A]  x  [c][n]
    unsigned* Bs = smem_dyn + 2*32*PAD_A;    // [2][64][PAD_B]  W' [o][c]

    const int nb    = blockIdx.x * 128;
    const int which = blockIdx.y >> 2;
    const int ob    = (blockIdx.y & 3) * 64;
    const int b     = blockIdx.z;

    const float* W    = g_wp + (size_t)(b*3 + which) * CC * CC;
    const float* bias = g_bp + (b*3 + which) * CC;
    const float* X    = x    + (size_t)b * CC * NQ;   // [c][n]

    const int tid  = threadIdx.x;
    const int wid  = tid >> 5, lane = tid & 31;
    const int wm   = wid & 1,  wn   = wid >> 1;
    const int g    = lane >> 2, t   = lane & 3;

    const unsigned as_base = (unsigned)__cvta_generic_to_shared(As);
    const unsigned bs_base = (unsigned)__cvta_generic_to_shared(Bs);

    const int a_c = tid >> 5, a_seg = tid & 31;   // 4 c-rows, 32 f4 segs
    const int b_o = tid >> 3, b_seg = tid & 7;    // 16 o-rows, 8 f4 segs

    #define LOAD_STAGE(s, c0)                                                  \
    {                                                                          \
        _Pragma("unroll")                                                      \
        for (int j = 0; j < 8; j++) {                                          \
            int c = a_c + j * 4;                                               \
            cp16(as_base + (((s)*32 + c) * PAD_A + a_seg * 4) * 4,             \
                 X + (size_t)((c0) + c) * NQ + nb + a_seg * 4);                \
        }                                                                      \
        _Pragma("unroll")                                                      \
        for (int j = 0; j < 4; j++) {                                          \
            int o = b_o + j * 16;                                              \
            cp16(bs_base + (((s)*64 + o) * PAD_B + b_seg * 4) * 4,             \
                 W + (size_t)(ob + o) * CC + (c0) + b_seg * 4);                \
        }                                                                      \
        CP_COMMIT();                                                           \
    }

    float acc[4][4][4];
    #pragma unroll
    for (int i = 0; i < 4; i++)
        #pragma unroll
        for (int j = 0; j < 4; j++)
            #pragma unroll
            for (int r = 0; r < 4; r++) acc[i][j][r] = 0.f;

    LOAD_STAGE(0, 0);

    #pragma unroll
    for (int ks = 0; ks < 8; ks++) {
        const int cur = ks & 1;
        if (ks < 7) {
            LOAD_STAGE(1 - cur, (ks + 1) * 32);
            CP_WAIT(1);
        } else {
            CP_WAIT(0);
        }
        __syncthreads();

        #pragma unroll
        for (int k8 = 0; k8 < 32; k8 += 8) {
            unsigned afr[4][4], bfr[4][2];
            #pragma unroll
            for (int mt = 0; mt < 4; mt++) {
                int row = wm * 64 + mt * 16;
                afr[mt][0] = As[(cur*32 + k8 + t    ) * PAD_A + row + g    ];
                afr[mt][1] = As[(cur*32 + k8 + t    ) * PAD_A + row + 8 + g];
                afr[mt][2] = As[(cur*32 + k8 + 4 + t) * PAD_A + row + g    ];
                afr[mt][3] = As[(cur*32 + k8 + 4 + t) * PAD_A + row + 8 + g];
            }
            #pragma unroll
            for (int nt = 0; nt < 4; nt++) {
                int col = wn * 32 + nt * 8;
                bfr[nt][0] = Bs[(cur*64 + col + g) * PAD_B + k8 + t    ];
                bfr[nt][1] = Bs[(cur*64 + col + g) * PAD_B + k8 + 4 + t];
            }
            #pragma unroll
            for (int mt = 0; mt < 4; mt++)
                #pragma unroll
                for (int nt = 0; nt < 4; nt++)
                    mma1688(acc[mt][nt], afr[mt], bfr[nt]);
        }
        __syncthreads();
    }
    #undef LOAD_STAGE

    if (which == 0) {
        float* O = g_qt + (size_t)b * NQ * CC;
        #pragma unroll
        for (int nt = 0; nt < 4; nt++) {
            int o = ob + wn * 32 + nt * 8 + 2 * t;
            float bb0 = bias[o], bb1 = bias[o + 1];
            #pragma unroll
            for (int mt = 0; mt < 4; mt++) {
                int n0 = nb + wm * 64 + mt * 16 + g;
                float2 v0 = {acc[mt][nt][0] + bb0, acc[mt][nt][1] + bb1};
                float2 v1 = {acc[mt][nt][2] + bb0, acc[mt][nt][3] + bb1};
                *(float2*)&O[(size_t)n0 * CC + o]       = v0;
                *(float2*)&O[(size_t)(n0 + 8) * CC + o] = v1;
            }
        }
    } else {
        __nv_bfloat16* O = (which == 1 ? g_kb : g_vb) + (size_t)b * NQ * CC;
        #pragma unroll
        for (int nt = 0; nt < 4; nt++) {
            int o = ob + wn * 32 + nt * 8 + 2 * t;
            float bb0 = bias[o], bb1 = bias[o + 1];
            #pragma unroll
            for (int mt = 0; mt < 4; mt++) {
                int n0 = nb + wm * 64 + mt * 16 + g;
                __nv_bfloat162 v0 = {__float2bfloat16_rn(acc[mt][nt][0] + bb0),
                                     __float2bfloat16_rn(acc[mt][nt][1] + bb1)};
                __nv_bfloat162 v1 = {__float2bfloat16_rn(acc[mt][nt][2] + bb0),
                                     __float2bfloat16_rn(acc[mt][nt][3] + bb1)};
                *(__nv_bfloat162*)&O[(size_t)n0 * CC + o]       = v0;
                *(__nv_bfloat162*)&O[(size_t)(n0 + 8) * CC + o] = v1;
            }
        }
    }
}

// ---------------------------------------------------------------------------
// Sparse attention: one warp per (b, n), all 4 heads (unchanged)
// ---------------------------------------------------------------------------
__device__ __forceinline__ void unpack8(float4 u, float* f) {
    const __nv_bfloat162* p = (const __nv_bfloat162*)&u;
    float2 a = __bfloat1622float2(p[0]);
    float2 b = __bfloat1622float2(p[1]);
    float2 c = __bfloat1622float2(p[2]);
    float2 d = __bfloat1622float2(p[3]);
    f[0]=a.x; f[1]=a.y; f[2]=b.x; f[3]=b.y;
    f[4]=c.x; f[5]=c.y; f[6]=d.x; f[7]=d.y;
}

__global__ void __launch_bounds__(256)
attn_kernel(const int* __restrict__ mask, const int* __restrict__ aidx)
{
    const int gw = (blockIdx.x * blockDim.x + threadIdx.x) >> 5;
    const int l  = threadIdx.x & 31;
    const int n  = gw & (NQ - 1);
    const int b  = gw >> 12;

    const float*         qp = g_qt + ((size_t)b * NQ + n) * CC;
    const __nv_bfloat16* Kb = g_kb + (size_t)b * NQ * CC;
    const __nv_bfloat16* Vb = g_vb + (size_t)b * NQ * CC;

    float qv[8];
    {
        float4 a = *(const float4*)&qp[8 * l];
        float4 c = *(const float4*)&qp[8 * l + 4];
        qv[0]=a.x; qv[1]=a.y; qv[2]=a.z; qv[3]=a.w;
        qv[4]=c.x; qv[5]=c.y; qv[6]=c.z; qv[7]=c.w;
    }

    const int idx0 = aidx[n * KK + l];
    const int idx1 = aidx[n * KK + l + 32];
    const int m0   = mask[n * KK + l];
    const int m1   = mask[n * KK + l + 32];

    float lg0[4] = {-INFINITY, -INFINITY, -INFINITY, -INFINITY};
    float lg1[4] = {-INFINITY, -INFINITY, -INFINITY, -INFINITY};

    #pragma unroll 4
    for (int kk = 0; kk < 32; kk++) {
        int mk = __shfl_sync(~0u, m0, kk);
        if (!mk) continue;
        int idx = __shfl_sync(~0u, idx0, kk);
        float kf[8];
        unpack8(((const float4*)(Kb + (size_t)idx * CC))[l], kf);
        float p = 0.f;
        #pragma unroll
        for (int j = 0; j < 8; j++) p += qv[j] * kf[j];
        p += __shfl_xor_sync(~0u, p, 4);
        p += __shfl_xor_sync(~0u, p, 2);
        p += __shfl_xor_sync(~0u, p, 1);
        float v0 = __shfl_sync(~0u, p, 0);
        float v1 = __shfl_sync(~0u, p, 8);
        float v2 = __shfl_sync(~0u, p, 16);
        float v3 = __shfl_sync(~0u, p, 24);
        if (kk == l) { lg0[0]=v0; lg0[1]=v1; lg0[2]=v2; lg0[3]=v3; }
    }
    #pragma unroll 4
    for (int kk = 0; kk < 32; kk++) {
        int mk = __shfl_sync(~0u, m1, kk);
        if (!mk) continue;
        int idx = __shfl_sync(~0u, idx1, kk);
        float kf[8];
        unpack8(((const float4*)(Kb + (size_t)idx * CC))[l], kf);
        float p = 0.f;
        #pragma unroll
        for (int j = 0; j < 8; j++) p += qv[j] * kf[j];
        p += __shfl_xor_sync(~0u, p, 4);
        p += __shfl_xor_sync(~0u, p, 2);
        p += __shfl_xor_sync(~0u, p, 1);
        float v0 = __shfl_sync(~0u, p, 0);
        float v1 = __shfl_sync(~0u, p, 8);
        float v2 = __shfl_sync(~0u, p, 16);
        float v3 = __shfl_sync(~0u, p, 24);
        if (kk == l) { lg1[0]=v0; lg1[1]=v1; lg1[2]=v2; lg1[3]=v3; }
    }

    float w0[4], w1[4];
    #pragma unroll
    for (int h = 0; h < 4; h++) {
        float mx = fmaxf(lg0[h], lg1[h]);
        #pragma unroll
        for (int o = 16; o; o >>= 1)
            mx = fmaxf(mx, __shfl_xor_sync(~0u, mx, o));
        float e0 = __expf(lg0[h] - mx);
        float e1 = __expf(lg1[h] - mx);
        float s = e0 + e1;
        #pragma unroll
        for (int o = 16; o; o >>= 1) s += __shfl_xor_sync(~0u, s, o);
        float inv = 1.f / s;
        w0[h] = e0 * inv;
        w1[h] = e1 * inv;
    }

    float acc[8] = {0.f,0.f,0.f,0.f,0.f,0.f,0.f,0.f};
    const int hsel = l >> 3;

    #pragma unroll 4
    for (int kk = 0; kk < 32; kk++) {
        int mk = __shfl_sync(~0u, m0, kk);
        if (!mk) continue;
        int idx = __shfl_sync(~0u, idx0, kk);
        float a0 = __shfl_sync(~0u, w0[0], kk);
        float a1 = __shfl_sync(~0u, w0[1], kk);
        float a2 = __shfl_sync(~0u, w0[2], kk);
        float a3 = __shfl_sync(~0u, w0[3], kk);
        float myw = hsel == 0 ? a0 : hsel == 1 ? a1 : hsel == 2 ? a2 : a3;
        float vf[8];
        unpack8(((const float4*)(Vb + (size_t)idx * CC))[l], vf);
        #pragma unroll
        for (int j = 0; j < 8; j++) acc[j] += myw * vf[j];
    }
    #pragma unroll 4
    for (int kk = 0; kk < 32; kk++) {
        int mk = __shfl_sync(~0u, m1, kk);
        if (!mk) continue;
        int idx = __shfl_sync(~0u, idx1, kk);
        float a0 = __shfl_sync(~0u, w1[0], kk);
        float a1 = __shfl_sync(~0u, w1[1], kk);
        float a2 = __shfl_sync(~0u, w1[2], kk);
        float a3 = __shfl_sync(~0u, w1[3], kk);
        float myw = hsel == 0 ? a0 : hsel == 1 ? a1 : hsel == 2 ? a2 : a3;
        float vf[8];
        unpack8(((const float4*)(Vb + (size_t)idx * CC))[l], vf);
        #pragma unroll
        for (int j = 0; j < 8; j++) acc[j] += myw * vf[j];
    }

    float* at = g_at + ((size_t)b * NQ + n) * CC;
    #pragma unroll
    for (int j = 0; j < 8; j++) {
        int c = 8 * l + j;
        int d = c & 63;
        at[d * HEADS + hsel] = acc[j];
    }
}

// ---------------------------------------------------------------------------
// Output projection + residual (tf32 MMA, cp.async double-buffered):
// out[b][o][n] = x[b][o][n] + sum_c Wo[o][c] * g_at[b][n][c] + bo[o]
// Tile 128(o=M) x 64(n=N), 128 threads. grid (NQ/64, CC/128, B).
// ---------------------------------------------------------------------------
#define OUT_SMEM ((2*128*PAD_B + 2*64*PAD_B) * 4)

__global__ void __launch_bounds__(128)
gemm_out(const float* __restrict__ Wo, const float* __restrict__ bo,
         const float* __restrict__ x,  float* __restrict__ out)
{
    extern __shared__ unsigned smem_dyn[];
    unsigned* As = smem_dyn;                   // [2][128][PAD_B]  Wo [o][c]
    unsigned* Bs = smem_dyn + 2*128*PAD_B;     // [2][64][PAD_B]   at [n][c]

    const int nb = blockIdx.x * 64, ob = blockIdx.y * 128, b = blockIdx.z;
    const float* A = g_at + (size_t)b * NQ * CC;   // [n][c]

    const int tid  = threadIdx.x;
    const int wid  = tid >> 5, lane = tid & 31;
    const int wm   = wid & 1,  wn   = wid >> 1;
    const int g    = lane >> 2, t   = lane & 3;

    const unsigned as_base = (unsigned)__cvta_generic_to_shared(As);
    const unsigned bs_base = (unsigned)__cvta_generic_to_shared(Bs);

    const int r_o = tid >> 3, r_seg = tid & 7;   // 16 rows, 8 f4 segs

    #define LOAD_STAGE(s, c0)                                                  \
    {                                                                          \
        _Pragma("unroll")                                                      \
        for (int j = 0; j < 8; j++) {                                          \
            int o = r_o + j * 16;                                              \
            cp16(as_base + (((s)*128 + o) * PAD_B + r_seg * 4) * 4,            \
                 Wo + (size_t)(ob + o) * CC + (c0) + r_seg * 4);               \
        }                                                                      \
        _Pragma("unroll")                                                      \
        for (int j = 0; j < 4; j++) {                                          \
            int n = r_o + j * 16;                                              \
            cp16(bs_base + (((s)*64 + n) * PAD_B + r_seg * 4) * 4,             \
                 A + (size_t)(nb + n) * CC + (c0) + r_seg * 4);                \
        }                                                                      \
        CP_COMMIT();                                                           \
    }

    float acc[4][4][4];
    #pragma unroll
    for (int i = 0; i < 4; i++)
        #pragma unroll
        for (int j = 0; j < 4; j++)
            #pragma unroll
            for (int r = 0; r < 4; r++) acc[i][j][r] = 0.f;

    LOAD_STAGE(0, 0);

    #pragma unroll
    for (int ks = 0; ks < 8; ks++) {
        const int cur = ks & 1;
        if (ks < 7) {
            LOAD_STAGE(1 - cur, (ks + 1) * 32);
            CP_WAIT(1);
        } else {
            CP_WAIT(0);
        }
        __syncthreads();

        #pragma unroll
        for (int k8 = 0; k8 < 32; k8 += 8) {
            unsigned afr[4][4], bfr[4][2];
            #pragma unroll
            for (int mt = 0; mt < 4; mt++) {
                int row = wm * 64 + mt * 16;
                afr[mt][0] = As[(cur*128 + row + g    ) * PAD_B + k8 + t    ];
                afr[mt][1] = As[(cur*128 + row + 8 + g) * PAD_B + k8 + t    ];
                afr[mt][2] = As[(cur*128 + row + g    ) * PAD_B + k8 + 4 + t];
                afr[mt][3] = As[(cur*128 + row + 8 + g) * PAD_B + k8 + 4 + t];
            }
            #pragma unroll
            for (int nt = 0; nt < 4; nt++) {
                int col = wn * 32 + nt * 8;
                bfr[nt][0] = Bs[(cur*64 + col + g) * PAD_B + k8 + t    ];
                bfr[nt][1] = Bs[(cur*64 + col + g) * PAD_B + k8 + 4 + t];
            }
            #pragma unroll
            for (int mt = 0; mt < 4; mt++)
                #pragma unroll
                for (int nt = 0; nt < 4; nt++)
                    mma1688(acc[mt][nt], afr[mt], bfr[nt]);
        }
        __syncthreads();
    }
    #undef LOAD_STAGE

    const float* xp = x   + (size_t)b * CC * NQ;
    float*       op = out + (size_t)b * CC * NQ;
    #pragma unroll
    for (int mt = 0; mt < 4; mt++) {
        int o0 = ob + wm * 64 + mt * 16 + g;
        float bb0 = bo[o0], bb1 = bo[o0 + 8];
        #pragma unroll
        for (int nt = 0; nt < 4; nt++) {
            int n = nb + wn * 32 + nt * 8 + 2 * t;
            size_t base0 = (size_t)o0 * NQ + n;
            size_t base1 = (size_t)(o0 + 8) * NQ + n;
            float2 x0 = *(const float2*)&xp[base0];
            float2 x1 = *(const float2*)&xp[base1];
            float2 v0 = {acc[mt][nt][0] + bb0 + x0.x, acc[mt][nt][1] + bb0 + x0.y};
            float2 v1 = {acc[mt][nt][2] + bb1 + x1.x, acc[mt][nt][3] + bb1 + x1.y};
            *(float2*)&op[base0] = v0;
            *(float2*)&op[base1] = v1;
        }
    }
}

// ---------------------------------------------------------------------------
extern "C" void kernel_launch(void* const* d_in, const int* in_sizes, int n_in,
                              void* d_out, int out_size)
{
    const float* x    = (const float*)d_in[0];
    const int*   mask = (const int*)  d_in[1];
    const int*   aidx = (const int*)  d_in[2];
    const float* gsc  = (const float*)d_in[3];
    const float* gbi  = (const float*)d_in[4];
    const float* wq   = (const float*)d_in[5];
    const float* bq   = (const float*)d_in[6];
    const float* wk   = (const float*)d_in[7];
    const float* bk   = (const float*)d_in[8];
    const float* wv   = (const float*)d_in[9];
    const float* bv   = (const float*)d_in[10];
    const float* wo   = (const float*)d_in[11];
    const float* bo   = (const float*)d_in[12];
    float* out = (float*)d_out;

    cudaFuncSetAttribute(gemm_qkv, cudaFuncAttributeMaxDynamicSharedMemorySize,
                         QKV_SMEM);
    cudaFuncSetAttribute(gemm_out, cudaFuncAttributeMaxDynamicSharedMemorySize,
                         OUT_SMEM);

    gn_stats<<<dim3(GROUPS, BB), 256>>>(x);

    wprep<<<dim3(3, BB), 256>>>(wq, bq, wk, bk, wv, bv, gsc, gbi);

    gemm_qkv<<<dim3(NQ / 128, 12, BB), 128, QKV_SMEM>>>(x);

    int total_warps = BB * NQ;
    attn_kernel<<<total_warps * 32 / 256, 256>>>(mask, aidx);

    gemm_out<<<dim3(NQ / 64, CC / 128, BB), 128, OUT_SMEM>>>(wo, bo, x, out);
}